// round 1
// baseline (speedup 1.0000x reference)
#include <cuda_runtime.h>
#include <cuda_bf16.h>

#define BATCH 8
#define NCLS 80
#define KPRE 256
#define MAXT 100
#define CAP 4096
#define NB2 256
#define NB3 2048

#define THRC (-2.4f)
#define VALID_THR (-2.9444389791664403f)
#define NEGV (-1000000000.0f)

// ---------------- static scratch (no allocations allowed) ----------------
__device__ int    g_cnt[BATCH * NCLS];
__device__ float  g_cs[BATCH * NCLS * CAP];
__device__ int    g_ci[BATCH * NCLS * CAP];
__device__ float4 g_boxes[BATCH * NCLS * KPRE];   // boxes_flat [B, C*KPRE, 4]
__device__ float  g_masked[BATCH * NCLS * KPRE];  // masked scores (sigmoid or NEG)
__device__ float  g_sel_s[BATCH * MAXT];
__device__ float4 g_sel_box[BATCH * MAXT];
__device__ float  g_sel_cls[BATCH * MAXT];
__device__ int    g_vdet[BATCH];

// monotone float <-> sortable uint
__device__ __forceinline__ unsigned fkey(float f) {
    unsigned b = __float_as_uint(f);
    return b ^ ((b & 0x80000000u) ? 0xFFFFFFFFu : 0x80000000u);
}
__device__ __forceinline__ float unfkey(unsigned u) {
    unsigned b = (u & 0x80000000u) ? (u ^ 0x80000000u) : ~u;
    return __uint_as_float(b);
}

// in-smem ascending bitonic sort of u64 keys, n power of two
__device__ void bitonic_sort(unsigned long long* key, int n) {
    for (int k = 2; k <= n; k <<= 1) {
        for (int j = k >> 1; j > 0; j >>= 1) {
            __syncthreads();
            for (int i = threadIdx.x; i < n; i += blockDim.x) {
                int ixj = i ^ j;
                if (ixj > i) {
                    unsigned long long a = key[i], b2 = key[ixj];
                    bool up = ((i & k) == 0);
                    if (up ? (a > b2) : (a < b2)) { key[i] = b2; key[ixj] = a; }
                }
            }
        }
    }
    __syncthreads();
}

// ---------------- K0: zero counters ----------------
__global__ void k_zero() {
    int i = blockIdx.x * blockDim.x + threadIdx.x;
    if (i < BATCH * NCLS) g_cnt[i] = 0;
}

// ---------------- K1: coalesced candidate collection ----------------
__global__ __launch_bounds__(256) void k_collect(const float* __restrict__ ycls, int A) {
    int total4 = BATCH * A * (NCLS / 4);
    for (int i = blockIdx.x * blockDim.x + threadIdx.x; i < total4;
         i += gridDim.x * blockDim.x) {
        float4 v = reinterpret_cast<const float4*>(ycls)[i];
        int base = i * 4;
        int c = base % NCLS;
        int ar = base / NCLS;
        int a = ar % A;
        int b = ar / A;
        int bc = b * NCLS + c;
        float vv[4] = {v.x, v.y, v.z, v.w};
#pragma unroll
        for (int t = 0; t < 4; t++) {
            if (vv[t] > THRC) {
                int p = atomicAdd(&g_cnt[bc + t], 1);
                if (p < CAP) {
                    g_cs[(bc + t) * CAP + p] = vv[t];
                    g_ci[(bc + t) * CAP + p] = a;
                }
            }
        }
    }
}

// ---------------- K2: per-(b,c) exact top-256 + decode + NMS ----------------
__global__ __launch_bounds__(256) void k_cls(const float* __restrict__ ybbox,
                                             const float* __restrict__ anchors, int A) {
    __shared__ unsigned long long skey[512];
    __shared__ float4 sbox[KPRE];
    __shared__ float slog[KPRE];
    __shared__ int shist[NB2];
    __shared__ unsigned smask[KPRE * 8];
    __shared__ unsigned skeep[8];
    __shared__ int scomp, sthr;

    int bc = blockIdx.x;
    int b = bc / NCLS;
    int tid = threadIdx.x;
    int cnt = min(g_cnt[bc], CAP);

    for (int i = tid; i < NB2; i += 256) shist[i] = 0;
    if (tid == 0) scomp = 0;
    __syncthreads();

    const float LO = -2.4f;
    const float INVW = (float)NB2 / 3.6f;  // range [-2.4, 1.2]
    const float* cs = &g_cs[bc * CAP];
    const int* ci = &g_ci[bc * CAP];

    for (int i = tid; i < cnt; i += 256) {
        float s = cs[i];
        int bin = (int)((s - LO) * INVW);
        bin = max(0, min(NB2 - 1, bin));
        atomicAdd(&shist[bin], 1);
    }
    __syncthreads();
    if (tid == 0) {
        int acc = 0, bthr = 0;
        for (int bj = NB2 - 1; bj >= 0; bj--) {
            acc += shist[bj];
            if (acc >= KPRE) { bthr = bj; break; }
        }
        sthr = bthr;
    }
    __syncthreads();
    int bthr = sthr;
    for (int i = tid; i < cnt; i += 256) {
        float s = cs[i];
        int bin = (int)((s - LO) * INVW);
        bin = max(0, min(NB2 - 1, bin));
        if (bin >= bthr) {
            int p = atomicAdd(&scomp, 1);
            if (p < 512) {
                unsigned kf = ~fkey(s);
                skey[p] = ((unsigned long long)kf << 32) | (unsigned)ci[i];
            }
        }
    }
    __syncthreads();
    int M = min(scomp, 512);
    for (int i = tid; i < 512; i += 256)
        if (i >= M) skey[i] = 0xFFFFFFFFFFFFFFFFULL;
    bitonic_sort(skey, 512);

    // decode top-256 boxes
    {
        unsigned long long key = skey[tid];
        unsigned a = (unsigned)key;
        float lg;
        if (a < (unsigned)A) {
            lg = unfkey(~(unsigned)(key >> 32));
            float4 an = reinterpret_cast<const float4*>(anchors)[a];
            float4 rl = reinterpret_cast<const float4*>(ybbox)[(size_t)b * A + a];
            float ha = an.z - an.x, wa = an.w - an.y;
            float cya = an.x + 0.5f * ha, cxa = an.y + 0.5f * wa;
            float cy = cya + rl.x * ha, cx = cxa + rl.y * wa;
            float h = ha * expf(rl.z), w = wa * expf(rl.w);
            sbox[tid] = make_float4(cy - 0.5f * h, cx - 0.5f * w, cy + 0.5f * h, cx + 0.5f * w);
        } else {
            lg = -1e30f;
            sbox[tid] = make_float4(0.f, 0.f, 0.f, 0.f);
        }
        slog[tid] = lg;
    }
    __syncthreads();

    // suppression bitmask: which j > i does box i suppress (iou > 0.5)
    {
        float4 bi = sbox[tid];
        float ai = (bi.z - bi.x) * (bi.w - bi.y);
        unsigned m[8] = {0, 0, 0, 0, 0, 0, 0, 0};
        for (int j = tid + 1; j < KPRE; j++) {
            float4 bj = sbox[j];
            float aj = (bj.z - bj.x) * (bj.w - bj.y);
            float ih = fmaxf(fminf(bi.z, bj.z) - fmaxf(bi.x, bj.x), 0.f);
            float iw = fmaxf(fminf(bi.w, bj.w) - fmaxf(bi.y, bj.y), 0.f);
            float inter = ih * iw;
            float iou = inter / (ai + aj - inter + 1e-8f);
            if (iou > 0.5f) m[j >> 5] |= 1u << (j & 31);
        }
#pragma unroll
        for (int w = 0; w < 8; w++) smask[tid * 8 + w] = m[w];
    }
    __syncthreads();

    if (tid == 0) {
        unsigned sup[8] = {0, 0, 0, 0, 0, 0, 0, 0};
        unsigned kb[8] = {0, 0, 0, 0, 0, 0, 0, 0};
        int c2 = 0;
        for (int i = 0; i < KPRE; i++) {
            bool valid = slog[i] > VALID_THR;
            bool supi = (sup[i >> 5] >> (i & 31)) & 1u;
            if (valid && !supi) {
                if (c2 < MAXT) kb[i >> 5] |= 1u << (i & 31);
                c2++;
#pragma unroll
                for (int w = 0; w < 8; w++) sup[w] |= smask[i * 8 + w];
            }
        }
#pragma unroll
        for (int w = 0; w < 8; w++) skeep[w] = kb[w];
    }
    __syncthreads();

    bool keep = (skeep[tid >> 5] >> (tid & 31)) & 1u;
    float sc = keep ? (1.f / (1.f + expf(-slog[tid]))) : NEGV;
    int flat = bc * KPRE + tid;  // == b*20480 + c*256 + tid
    g_masked[flat] = sc;
    g_boxes[flat] = sbox[tid];
}

// ---------------- K3: per-batch exact top-100 of masked scores ----------------
__global__ __launch_bounds__(256) void k_sel() {
    __shared__ int shist[NB3];
    __shared__ unsigned long long skey[512];
    __shared__ int scomp, sthr, stot;
    int b = blockIdx.x;
    int tid = threadIdx.x;
    for (int i = tid; i < NB3; i += 256) shist[i] = 0;
    if (tid == 0) scomp = 0;
    __syncthreads();
    const float* mk = &g_masked[b * NCLS * KPRE];
    const int N = NCLS * KPRE;
    for (int i = tid; i < N; i += 256) {
        float s = mk[i];
        if (s > 0.f) {
            int bin = min((int)(s * (float)NB3), NB3 - 1);
            atomicAdd(&shist[bin], 1);
        }
    }
    __syncthreads();
    if (tid == 0) {
        int acc = 0, bthr = -1;
        for (int bj = NB3 - 1; bj >= 0; bj--) {
            acc += shist[bj];
            if (bthr < 0 && acc >= MAXT) bthr = bj;
        }
        if (bthr < 0) bthr = 0;
        sthr = bthr;
        stot = acc;
    }
    __syncthreads();
    int bthr = sthr;
    for (int i = tid; i < N; i += 256) {
        float s = mk[i];
        if (s > 0.f) {
            int bin = min((int)(s * (float)NB3), NB3 - 1);
            if (bin >= bthr) {
                int p = atomicAdd(&scomp, 1);
                if (p < 512) {
                    unsigned kf = ~fkey(s);
                    skey[p] = ((unsigned long long)kf << 32) | (unsigned)i;
                }
            }
        }
    }
    __syncthreads();
    int M = min(scomp, 512);
    for (int i = tid; i < 512; i += 256)
        if (i >= M) skey[i] = 0xFFFFFFFFFFFFFFFFULL;
    bitonic_sort(skey, 512);

    int vd = min(stot, MAXT);
    if (tid < MAXT) {
        unsigned long long key = skey[tid];
        unsigned fl = (unsigned)key;
        bool valid = tid < vd;
        float s = 0.f, cl = 0.f;
        float4 bx = make_float4(0.f, 0.f, 0.f, 0.f);
        if (valid) {
            s = unfkey(~(unsigned)(key >> 32));
            bx = g_boxes[b * N + fl];
            cl = (float)(fl >> 8);
        }
        g_sel_s[b * MAXT + tid] = s;
        g_sel_box[b * MAXT + tid] = bx;
        g_sel_cls[b * MAXT + tid] = cl;
    }
    if (tid == 0) g_vdet[b] = vd;
}

// ---------------- K4: rescale + final NMS + stable partition + output ----------------
__global__ __launch_bounds__(128) void k_final(const int* __restrict__ hs,
                                               const int* __restrict__ ws,
                                               float* __restrict__ out) {
    __shared__ float4 srb[MAXT];
    __shared__ unsigned smask[MAXT * 4];
    __shared__ unsigned skeep[4];
    int b = blockIdx.x;
    int tid = threadIdx.x;
    float H = (float)hs[b], W = (float)ws[b];
    float rh = H / 512.f, rw = W / 512.f;

    if (tid < MAXT) {
        float4 bx = g_sel_box[b * MAXT + tid];
        float y1 = fminf(fmaxf(bx.x * rh, 0.f), H);
        float x1 = fminf(fmaxf(bx.y * rw, 0.f), W);
        float y2 = fminf(fmaxf(bx.z * rh, 0.f), H);
        float x2 = fminf(fmaxf(bx.w * rw, 0.f), W);
        srb[tid] = make_float4(y1, x1, y2, x2);
    }
    __syncthreads();
    if (tid < MAXT) {
        float4 bi = srb[tid];
        float ai = (bi.z - bi.x) * (bi.w - bi.y);
        unsigned m[4] = {0, 0, 0, 0};
        for (int j = tid + 1; j < MAXT; j++) {
            float4 bj = srb[j];
            float aj = (bj.z - bj.x) * (bj.w - bj.y);
            float ih = fmaxf(fminf(bi.z, bj.z) - fmaxf(bi.x, bj.x), 0.f);
            float iw = fmaxf(fminf(bi.w, bj.w) - fmaxf(bi.y, bj.y), 0.f);
            float inter = ih * iw;
            float iou = inter / (ai + aj - inter + 1e-8f);
            if (iou > 0.7f) m[j >> 5] |= 1u << (j & 31);
        }
#pragma unroll
        for (int w = 0; w < 4; w++) smask[tid * 4 + w] = m[w];
    }
    __syncthreads();
    if (tid == 0) {
        int vd = g_vdet[b];
        unsigned sup[4] = {0, 0, 0, 0};
        unsigned kb[4] = {0, 0, 0, 0};
        for (int i = 0; i < MAXT; i++) {
            bool valid = i < vd;
            bool supi = (sup[i >> 5] >> (i & 31)) & 1u;
            if (valid && !supi) {
                kb[i >> 5] |= 1u << (i & 31);
#pragma unroll
                for (int w = 0; w < 4; w++) sup[w] |= smask[i * 4 + w];
            }
        }
#pragma unroll
        for (int w = 0; w < 4; w++) skeep[w] = kb[w];
    }
    __syncthreads();

    float* ob = out + b * (MAXT * 4);
    float* os = out + BATCH * MAXT * 4 + b * MAXT;
    float* oc = out + BATCH * MAXT * 4 + BATCH * MAXT + b * MAXT;
    for (int i = tid; i < MAXT * 4; i += 128) ob[i] = 0.f;
    for (int i = tid; i < MAXT; i += 128) { os[i] = 0.f; oc[i] = 0.f; }
    __syncthreads();
    if (tid == 0) {
        int nv = 0;
        for (int i = 0; i < MAXT; i++) {
            if ((skeep[i >> 5] >> (i & 31)) & 1u) {
                float4 r = srb[i];
                ob[nv * 4 + 0] = r.x;
                ob[nv * 4 + 1] = r.y;
                ob[nv * 4 + 2] = r.z;
                ob[nv * 4 + 3] = r.w;
                os[nv] = g_sel_s[b * MAXT + i];
                oc[nv] = g_sel_cls[b * MAXT + i];
                nv++;
            }
        }
        out[BATCH * MAXT * 4 + 2 * BATCH * MAXT + b] = (float)nv;
    }
}

// ---------------- launcher ----------------
extern "C" void kernel_launch(void* const* d_in, const int* in_sizes, int n_in,
                              void* d_out, int out_size) {
    const float* ycls = (const float*)d_in[0];
    const float* ybb  = (const float*)d_in[1];
    const float* anc  = (const float*)d_in[2];
    const int*   hs   = (const int*)d_in[3];
    const int*   ws   = (const int*)d_in[4];
    int A = in_sizes[2] / 4;

    k_zero<<<(BATCH * NCLS + 255) / 256, 256>>>();
    k_collect<<<2048, 256>>>(ycls, A);
    k_cls<<<BATCH * NCLS, 256>>>(ybb, anc, A);
    k_sel<<<BATCH, 256>>>();
    k_final<<<BATCH, 128>>>(hs, ws, (float*)d_out);
}

// round 2
// speedup vs baseline: 4.7711x; 4.7711x over previous
#include <cuda_runtime.h>
#include <cuda_bf16.h>

#define BATCH 8
#define NCLS 80
#define KPRE 256
#define MAXT 100
#define CAP 4096
#define NB2 256
#define NB3 2048
#define APB 192      // anchors per collect block
#define STG 48       // smem staging entries per class per block

#define THRC (-2.4f)
#define VALID_THR (-2.9444389791664403f)

// ---------------- static scratch ----------------
__device__ int    g_cnt[BATCH * NCLS];
__device__ float  g_cs[BATCH * NCLS * CAP];
__device__ int    g_ci[BATCH * NCLS * CAP];
__device__ float4 g_boxes[BATCH * NCLS * KPRE];   // boxes_flat [B, C*KPRE, 4]
__device__ float  g_masked[BATCH * NCLS * KPRE];  // sigmoid if kept else 0-ish sentinel

// monotone float <-> sortable uint
__device__ __forceinline__ unsigned fkey(float f) {
    unsigned b = __float_as_uint(f);
    return b ^ ((b & 0x80000000u) ? 0xFFFFFFFFu : 0x80000000u);
}
__device__ __forceinline__ float unfkey(unsigned u) {
    unsigned b = (u & 0x80000000u) ? (u ^ 0x80000000u) : ~u;
    return __uint_as_float(b);
}

// in-smem ascending bitonic sort of 512 u64 keys, 256 threads
__device__ void bitonic_sort512(unsigned long long* key) {
    for (int k = 2; k <= 512; k <<= 1) {
        for (int j = k >> 1; j > 0; j >>= 1) {
            __syncthreads();
            for (int i = threadIdx.x; i < 512; i += 256) {
                int ixj = i ^ j;
                if (ixj > i) {
                    unsigned long long a = key[i], b2 = key[ixj];
                    bool up = ((i & k) == 0);
                    if (up ? (a > b2) : (a < b2)) { key[i] = b2; key[ixj] = a; }
                }
            }
        }
    }
    __syncthreads();
}

// ---------------- K0: zero counters ----------------
__global__ void k_zero() {
    int i = blockIdx.x * blockDim.x + threadIdx.x;
    if (i < BATCH * NCLS) g_cnt[i] = 0;
}

// ---------------- K1: collection with smem-privatized counters ----------------
__global__ __launch_bounds__(256) void k_collect(const float* __restrict__ ycls, int A) {
    __shared__ int scnt[NCLS];
    __shared__ int sbase[NCLS];
    __shared__ unsigned long long sstage[NCLS * STG];

    int b = blockIdx.y;
    int a0 = blockIdx.x * APB;
    int tid = threadIdx.x;
    for (int i = tid; i < NCLS; i += 256) scnt[i] = 0;
    __syncthreads();

    int nA = min(APB, A - a0);
    int ne4 = nA * (NCLS / 4);
    const float4* src = reinterpret_cast<const float4*>(ycls + ((size_t)b * A + a0) * NCLS);
    int cbase = b * NCLS;

    for (int i = tid; i < ne4; i += 256) {
        float4 v = src[i];
        int e = i * 4;
        int al = e / NCLS;
        int c = e - al * NCLS;
        int a = a0 + al;
        float vv[4] = {v.x, v.y, v.z, v.w};
#pragma unroll
        for (int t = 0; t < 4; t++) {
            if (vv[t] > THRC) {
                int cc = c + t;
                int p = atomicAdd(&scnt[cc], 1);
                if (p < STG) {
                    sstage[cc * STG + p] =
                        ((unsigned long long)__float_as_uint(vv[t]) << 32) | (unsigned)a;
                } else {  // overflow fallback (astronomically rare) keeps exactness
                    int gp = atomicAdd(&g_cnt[cbase + cc], 1);
                    if (gp < CAP) {
                        g_cs[(cbase + cc) * CAP + gp] = vv[t];
                        g_ci[(cbase + cc) * CAP + gp] = a;
                    }
                }
            }
        }
    }
    __syncthreads();
    if (tid < NCLS) {
        int n = min(scnt[tid], STG);
        sbase[tid] = atomicAdd(&g_cnt[cbase + tid], n);
    }
    __syncthreads();
    for (int idx = tid; idx < NCLS * STG; idx += 256) {
        int c = idx / STG, k = idx % STG;
        if (k < min(scnt[c], STG)) {
            int gp = sbase[c] + k;
            if (gp < CAP) {
                unsigned long long pk = sstage[c * STG + k];
                g_cs[(cbase + c) * CAP + gp] = __uint_as_float((unsigned)(pk >> 32));
                g_ci[(cbase + c) * CAP + gp] = (int)(unsigned)pk;
            }
        }
    }
}

// ---------------- K2: per-(b,c) top-256 + decode + NMS ----------------
__global__ __launch_bounds__(256) void k_cls(const float* __restrict__ ybbox,
                                             const float* __restrict__ anchors, int A) {
    __shared__ unsigned long long skey[512];
    __shared__ float4 sbox[KPRE];
    __shared__ float slog[KPRE];
    __shared__ int shist[NB2];
    __shared__ int ssuf[NB2];
    __shared__ unsigned skeepw[8];
    __shared__ int scomp, sthr, schg;

    int bc = blockIdx.x;
    int b = bc / NCLS;
    int tid = threadIdx.x;
    int w = tid >> 5, lane = tid & 31;
    int cnt = min(g_cnt[bc], CAP);

    shist[tid] = 0;
    if (tid == 0) { scomp = 0; sthr = 0; }
    __syncthreads();

    const float LO = -2.4f;
    const float INVW = (float)NB2 / 3.6f;  // logit range [-2.4, 1.2]
    const float* cs = &g_cs[bc * CAP];
    const int* ci = &g_ci[bc * CAP];

    for (int i = tid; i < cnt; i += 256) {
        float s = cs[i];
        int bin = max(0, min(NB2 - 1, (int)((s - LO) * INVW)));
        atomicAdd(&shist[bin], 1);
    }
    __syncthreads();
    // parallel suffix scan over 256 bins
    ssuf[tid] = shist[tid];
    __syncthreads();
    for (int d = 1; d < 256; d <<= 1) {
        int v = (tid + d < 256) ? ssuf[tid + d] : 0;
        __syncthreads();
        ssuf[tid] += v;
        __syncthreads();
    }
    {
        int after = (tid < 255) ? ssuf[tid + 1] : 0;
        if (ssuf[tid] >= KPRE && after < KPRE) sthr = tid;
    }
    __syncthreads();
    int bthr = sthr;
    for (int i = tid; i < cnt; i += 256) {
        float s = cs[i];
        int bin = max(0, min(NB2 - 1, (int)((s - LO) * INVW)));
        if (bin >= bthr) {
            int p = atomicAdd(&scomp, 1);
            if (p < 512) {
                unsigned kf = ~fkey(s);
                skey[p] = ((unsigned long long)kf << 32) | (unsigned)ci[i];
            }
        }
    }
    __syncthreads();
    int M = min(scomp, 512);
    for (int i = tid; i < 512; i += 256)
        if (i >= M) skey[i] = 0xFFFFFFFFFFFFFFFFULL;
    bitonic_sort512(skey);

    // decode top-256 boxes
    {
        unsigned long long key = skey[tid];
        unsigned a = (unsigned)key;
        float lg;
        if (a < (unsigned)A) {
            lg = unfkey(~(unsigned)(key >> 32));
            float4 an = reinterpret_cast<const float4*>(anchors)[a];
            float4 rl = reinterpret_cast<const float4*>(ybbox)[(size_t)b * A + a];
            float ha = an.z - an.x, wa = an.w - an.y;
            float cya = an.x + 0.5f * ha, cxa = an.y + 0.5f * wa;
            float cy = cya + rl.x * ha, cx = cxa + rl.y * wa;
            float h = ha * expf(rl.z), wd = wa * expf(rl.w);
            sbox[tid] = make_float4(cy - 0.5f * h, cx - 0.5f * wd, cy + 0.5f * h, cx + 0.5f * wd);
        } else {
            lg = -1e30f;
            sbox[tid] = make_float4(0.f, 0.f, 0.f, 0.f);
        }
        slog[tid] = lg;
    }
    __syncthreads();

    // suppressed-by masks (j < i), kept in registers
    unsigned m[8] = {0, 0, 0, 0, 0, 0, 0, 0};
    {
        float4 bi = sbox[tid];
        float ai = (bi.z - bi.x) * (bi.w - bi.y);
        for (int j = 0; j < tid; j++) {
            float4 bj = sbox[j];
            float aj = (bj.z - bj.x) * (bj.w - bj.y);
            float ih = fmaxf(fminf(bi.z, bj.z) - fmaxf(bi.x, bj.x), 0.f);
            float iw = fmaxf(fminf(bi.w, bj.w) - fmaxf(bi.y, bj.y), 0.f);
            float inter = ih * iw;
            if (inter > 0.5f * (ai + aj - inter + 1e-8f)) m[j >> 5] |= 1u << (j & 31);
        }
    }
    bool valid_i = slog[tid] > VALID_THR;
    unsigned vb = __ballot_sync(0xFFFFFFFFu, valid_i);
    if (lane == 0) skeepw[w] = vb;
    __syncthreads();

    // Jacobi fixed-point greedy NMS (exact: unique fixed point = greedy)
    for (int it = 0; it <= KPRE; it++) {
        unsigned kw[8];
#pragma unroll
        for (int u = 0; u < 8; u++) kw[u] = skeepw[u];
        unsigned supb = 0;
#pragma unroll
        for (int u = 0; u < 8; u++) supb |= (m[u] & kw[u]);
        bool nk = valid_i && (supb == 0);
        unsigned nw = __ballot_sync(0xFFFFFFFFu, nk);
        __syncthreads();
        if (tid == 0) schg = 0;
        __syncthreads();
        if (lane == 0 && nw != kw[w]) { skeepw[w] = nw; schg = 1; }
        __syncthreads();
        if (!schg) break;
    }

    // rank-cap (<100 among kept) + output
    {
        int rank = 0;
        bool kept = false;
#pragma unroll
        for (int u = 0; u < 8; u++) {
            unsigned kwu = skeepw[u];
            if (u < w) rank += __popc(kwu);
            else if (u == w) {
                rank += __popc(kwu & ((lane == 0) ? 0u : (0xFFFFFFFFu >> (32 - lane))));
                kept = (kwu >> lane) & 1u;
            }
        }
        bool kfin = kept && (rank < MAXT);
        float sc = kfin ? (1.f / (1.f + expf(-slog[tid]))) : -1.f;
        int flat = bc * KPRE + tid;
        g_masked[flat] = sc;
        g_boxes[flat] = sbox[tid];
    }
}

// ---------------- K3: fused per-batch top-100 + rescale + final NMS + output ----------------
__global__ __launch_bounds__(256) void k_selfinal(const int* __restrict__ hs,
                                                  const int* __restrict__ ws,
                                                  float* __restrict__ out) {
    __shared__ int shist[NB3];
    __shared__ int ssuf[256];
    __shared__ unsigned long long skey[512];
    __shared__ float4 srb[MAXT];
    __shared__ float s_s[MAXT];
    __shared__ float s_c[MAXT];
    __shared__ unsigned skeepw[4];
    __shared__ int scomp, sthr, stot, schg;

    int b = blockIdx.x;
    int tid = threadIdx.x;
    int w = tid >> 5, lane = tid & 31;
    for (int i = tid; i < NB3; i += 256) shist[i] = 0;
    if (tid == 0) { scomp = 0; sthr = 0; stot = 0; }
    __syncthreads();

    const float* mk = &g_masked[b * NCLS * KPRE];
    const int N = NCLS * KPRE;
    for (int i = tid; i < N; i += 256) {
        float s = mk[i];
        if (s > 0.f) atomicAdd(&shist[min((int)(s * (float)NB3), NB3 - 1)], 1);
    }
    __syncthreads();
    // two-level suffix scan over 2048 bins (8 per thread)
    {
        int base = tid * 8, csum = 0;
#pragma unroll
        for (int k = 0; k < 8; k++) csum += shist[base + k];
        ssuf[tid] = csum;
        __syncthreads();
        for (int d = 1; d < 256; d <<= 1) {
            int v = (tid + d < 256) ? ssuf[tid + d] : 0;
            __syncthreads();
            ssuf[tid] += v;
            __syncthreads();
        }
        if (tid == 0) stot = ssuf[0];
        int after = (tid < 255) ? ssuf[tid + 1] : 0;
        if (ssuf[tid] >= MAXT && after < MAXT) {
            int acc = after, bthr = base;
            for (int bj = base + 7; bj >= base; bj--) {
                acc += shist[bj];
                if (acc >= MAXT) { bthr = bj; break; }
            }
            sthr = bthr;
        }
    }
    __syncthreads();
    int bthr = sthr;
    for (int i = tid; i < N; i += 256) {
        float s = mk[i];
        if (s > 0.f) {
            int bin = min((int)(s * (float)NB3), NB3 - 1);
            if (bin >= bthr) {
                int p = atomicAdd(&scomp, 1);
                if (p < 512) {
                    unsigned kf = ~fkey(s);
                    skey[p] = ((unsigned long long)kf << 32) | (unsigned)i;
                }
            }
        }
    }
    __syncthreads();
    int M = min(scomp, 512);
    for (int i = tid; i < 512; i += 256)
        if (i >= M) skey[i] = 0xFFFFFFFFFFFFFFFFULL;
    bitonic_sort512(skey);

    int vd = min(stot, MAXT);
    float H = (float)hs[b], W = (float)ws[b];
    float rh = H / 512.f, rw = W / 512.f;
    if (tid < MAXT) {
        unsigned long long key = skey[tid];
        unsigned fl = (unsigned)key;
        float s = 0.f, cl = 0.f;
        float4 bx = make_float4(0.f, 0.f, 0.f, 0.f);
        if (tid < vd) {
            s = unfkey(~(unsigned)(key >> 32));
            float4 raw = g_boxes[b * N + fl];
            cl = (float)(fl >> 8);
            bx.x = fminf(fmaxf(raw.x * rh, 0.f), H);
            bx.y = fminf(fmaxf(raw.y * rw, 0.f), W);
            bx.z = fminf(fmaxf(raw.z * rh, 0.f), H);
            bx.w = fminf(fmaxf(raw.w * rw, 0.f), W);
        }
        srb[tid] = bx;
        s_s[tid] = s;
        s_c[tid] = cl;
    }
    __syncthreads();

    // suppressed-by masks (j < i), registers
    unsigned m[4] = {0, 0, 0, 0};
    bool valid_i = (tid < vd);
    if (tid < MAXT) {
        float4 bi = srb[tid];
        float ai = (bi.z - bi.x) * (bi.w - bi.y);
        for (int j = 0; j < tid && j < MAXT; j++) {
            float4 bj = srb[j];
            float aj = (bj.z - bj.x) * (bj.w - bj.y);
            float ih = fmaxf(fminf(bi.z, bj.z) - fmaxf(bi.x, bj.x), 0.f);
            float iw = fmaxf(fminf(bi.w, bj.w) - fmaxf(bi.y, bj.y), 0.f);
            float inter = ih * iw;
            if (inter > 0.7f * (ai + aj - inter + 1e-8f)) m[j >> 5] |= 1u << (j & 31);
        }
    }
    unsigned vb = __ballot_sync(0xFFFFFFFFu, valid_i);
    if (lane == 0 && w < 4) skeepw[w] = vb;
    __syncthreads();

    for (int it = 0; it <= MAXT + 1; it++) {
        unsigned kw[4];
#pragma unroll
        for (int u = 0; u < 4; u++) kw[u] = skeepw[u];
        unsigned supb = 0;
#pragma unroll
        for (int u = 0; u < 4; u++) supb |= (m[u] & kw[u]);
        bool nk = valid_i && (supb == 0);
        unsigned nw = __ballot_sync(0xFFFFFFFFu, nk);
        __syncthreads();
        if (tid == 0) schg = 0;
        __syncthreads();
        if (lane == 0 && w < 4 && nw != kw[w]) { skeepw[w] = nw; schg = 1; }
        __syncthreads();
        if (!schg) break;
    }

    // zero the batch's output slices, then compacted scatter
    float* ob = out + b * (MAXT * 4);
    float* os = out + BATCH * MAXT * 4 + b * MAXT;
    float* oc = out + BATCH * MAXT * 4 + BATCH * MAXT + b * MAXT;
    for (int i = tid; i < MAXT * 4; i += 256) ob[i] = 0.f;
    for (int i = tid; i < MAXT; i += 256) { os[i] = 0.f; oc[i] = 0.f; }
    __syncthreads();

    if (tid < MAXT) {
        bool kept = (skeepw[w] >> lane) & 1u;
        int rank = 0;
#pragma unroll
        for (int u = 0; u < 4; u++) {
            unsigned kwu = skeepw[u];
            if (u < w) rank += __popc(kwu);
            else if (u == w) rank += __popc(kwu & ((lane == 0) ? 0u : (0xFFFFFFFFu >> (32 - lane))));
        }
        if (kept) {
            float4 r = srb[tid];
            ob[rank * 4 + 0] = r.x;
            ob[rank * 4 + 1] = r.y;
            ob[rank * 4 + 2] = r.z;
            ob[rank * 4 + 3] = r.w;
            os[rank] = s_s[tid];
            oc[rank] = s_c[tid];
        }
    }
    if (tid == 0) {
        int nv = __popc(skeepw[0]) + __popc(skeepw[1]) + __popc(skeepw[2]) + __popc(skeepw[3]);
        out[BATCH * MAXT * 4 + 2 * BATCH * MAXT + b] = (float)nv;
    }
}

// ---------------- launcher ----------------
extern "C" void kernel_launch(void* const* d_in, const int* in_sizes, int n_in,
                              void* d_out, int out_size) {
    const float* ycls = (const float*)d_in[0];
    const float* ybb  = (const float*)d_in[1];
    const float* anc  = (const float*)d_in[2];
    const int*   hs   = (const int*)d_in[3];
    const int*   ws   = (const int*)d_in[4];
    int A = in_sizes[2] / 4;

    k_zero<<<(BATCH * NCLS + 255) / 256, 256>>>();
    dim3 cg((A + APB - 1) / APB, BATCH);
    k_collect<<<cg, 256>>>(ycls, A);
    k_cls<<<BATCH * NCLS, 256>>>(ybb, anc, A);
    k_selfinal<<<BATCH, 256>>>(hs, ws, (float*)d_out);
}